// round 8
// baseline (speedup 1.0000x reference)
#include <cuda_runtime.h>

// ---------------------------------------------------------------------------
// MOE_DISTRIBUTE_CASCADE_GRAPH — SINGLE-LAUNCH fused version.
//   inv[i]   = stable counting-sort rank of expert_ids.flat[i]   (N = B*K)
//   out[b,h] = sum_k scales[b,k] * G[inv[b*K+k], h]
//   output   = (out, out) concatenated (2*B*H floats)
//
// Launch-node overhead (~5-10us per serialized graph node, measured across
// R1/R2/R6/R7) dominated the non-combine time. So: ONE kernel. Block (0,0)
// computes the full rank (8 warps, match-based, ~10us) and releases a device
// flag; all other blocks spin (wave-1 only; later waves see flag set). The
// last block resets the flag -> deterministic across graph replays.
// ---------------------------------------------------------------------------

#define NBINS   256        // max experts supported (dataset uses 64)
#define MAXN    65536      // max B*K supported (dataset uses 32768)

__device__ int g_inv[MAXN];
__device__ int g_flag = 0;          // rank-done flag (reset by last block)
__device__ unsigned g_done = 0;     // completion counter

// fallback scratch (generic path, 3-kernel)
#define NCHUNK  256
#define CHSZ    256
__device__ int g_hist[NBINS * NCHUNK];
__device__ int g_base[NBINS * NCHUNK];
__device__ int g_ebase[NBINS];

// --- one match-based stable-rank step (warp-converged, FULL mask) ----------
__device__ __forceinline__ void rank_step(int id, int idx, int lane,
                                          int* mycnt) {
    const unsigned FULL = 0xffffffffu;
    const bool valid = (id >= 0);
    const int  key   = valid ? id : (NBINS + lane);     // singleton if invalid
    const unsigned mask = __match_any_sync(FULL, key);
    const int lower  = __popc(mask & ((1u << lane) - 1u));
    const int leader = __ffs(mask) - 1;
    int c0 = 0;
    if (valid && lane == leader) {
        c0 = mycnt[key];
        mycnt[key] = c0 + __popc(mask);
    }
    c0 = __shfl_sync(FULL, c0, leader);
    if (valid) g_inv[idx] = c0 + lower;                 // warp-local rank
    __syncwarp();
}

// --- fused single-launch kernel ---------------------------------------------
template <int K, bool GUARD>
__global__ void __launch_bounds__(256, 4)
fused_kernel(const int* __restrict__ ids,
             const float* __restrict__ scales,
             const float* __restrict__ G,
             float* __restrict__ out,
             int B, int H4, int dup, int n) {
    __shared__ int   cnt[8 * NBINS];     // rank counters (block 0 only)
    __shared__ int   totals[NBINS];
    __shared__ int   rows[K];
    __shared__ float sc[K];

    const int tid = threadIdx.x;
    const int b   = blockIdx.y;

    // scales don't depend on the rank -> prefetch before any waiting
    if (tid < K) sc[tid] = scales[b * K + tid];

    if (blockIdx.x == 0 && blockIdx.y == 0) {
        // ================= RANK (8 warps, all of N) =================
        const int w    = tid >> 5;
        const int lane = tid & 31;
        const int cpw  = (n + 7) / 8;
        const int beg  = w * cpw;
        const int end  = min(beg + cpw, n);
        const int rounds = (end - beg + 31) / 32;

        for (int j = tid; j < 8 * NBINS; j += 256) cnt[j] = 0;
        __syncthreads();

        int* mycnt = &cnt[w * NBINS];
        // pass 1: warp-local stable ranks + per-warp histograms
        #pragma unroll 4
        for (int r = 0; r < rounds; r++) {
            const int i  = beg + r * 32 + lane;
            const int id = (i < end) ? __ldg(&ids[i]) : -1;
            rank_step(id, i, lane, mycnt);
        }
        __syncthreads();

        // scan 1: per-expert exclusive scan over the 8 warp rows
        if (tid < NBINS) {
            int run = 0;
            #pragma unroll
            for (int ww = 0; ww < 8; ww++) {
                const int h = cnt[ww * NBINS + tid];
                cnt[ww * NBINS + tid] = run;
                run += h;
            }
            totals[tid] = run;
        }
        __syncthreads();

        // scan 2: in-place inclusive Hillis-Steele over expert totals
        #pragma unroll
        for (int d = 1; d < NBINS; d <<= 1) {
            const int v = (tid >= d) ? totals[tid - d] : 0;
            __syncthreads();
            totals[tid] += v;
            __syncthreads();
        }
        if (tid < NBINS) {
            const int base = (tid == 0) ? 0 : totals[tid - 1];
            #pragma unroll
            for (int ww = 0; ww < 8; ww++)
                cnt[ww * NBINS + tid] += base;
        }
        __syncthreads();

        // pass 2: add global bases (independent iterations, ids L1-warm)
        #pragma unroll 4
        for (int r = 0; r < rounds; r++) {
            const int i = beg + r * 32 + lane;
            if (i < end) g_inv[i] += mycnt[__ldg(&ids[i])];
        }
        __threadfence();                 // publish g_inv before the flag
        __syncthreads();
        if (tid == 0) atomicExch(&g_flag, 1);
    } else {
        // ================= WAIT for rank =================
        if (tid == 0) {
            while (atomicAdd(&g_flag, 0) == 0) __nanosleep(128);
        }
        __syncthreads();                 // flag seen -> g_inv is in L2
    }

    // ================= COMBINE (HBM streaming roofline) =================
    if (tid < K) rows[tid] = __ldcg(&g_inv[b * K + tid]);  // L2-fresh
    __syncthreads();

    const int h0 = blockIdx.x * 512 + tid;
    const int h1 = h0 + 256;
    const float4* __restrict__ Gv = reinterpret_cast<const float4*>(G);
    float4* __restrict__ ov = reinterpret_cast<float4*>(out);

    const bool v0 = GUARD ? (h0 < H4) : true;
    const bool v1 = GUARD ? (h1 < H4) : true;
    float4 acc0 = make_float4(0.f, 0.f, 0.f, 0.f);
    float4 acc1 = make_float4(0.f, 0.f, 0.f, 0.f);
    #pragma unroll
    for (int k = 0; k < K; k++) {
        const float  s  = sc[k];
        const size_t rb = (size_t)rows[k] * H4;
        if (v0) {
            const float4 a = __ldg(&Gv[rb + h0]);
            acc0.x = fmaf(s, a.x, acc0.x);
            acc0.y = fmaf(s, a.y, acc0.y);
            acc0.z = fmaf(s, a.z, acc0.z);
            acc0.w = fmaf(s, a.w, acc0.w);
        }
        if (v1) {
            const float4 c = __ldg(&Gv[rb + h1]);
            acc1.x = fmaf(s, c.x, acc1.x);
            acc1.y = fmaf(s, c.y, acc1.y);
            acc1.z = fmaf(s, c.z, acc1.z);
            acc1.w = fmaf(s, c.w, acc1.w);
        }
    }
    const size_t ob = (size_t)b * H4;
    if (v0) ov[ob + h0] = acc0;
    if (v1) ov[ob + h1] = acc1;
    if (dup) {
        const size_t od = (size_t)B * H4 + ob;
        if (v0) ov[od + h0] = acc0;
        if (v1) ov[od + h1] = acc1;
    }

    // ================= RESET (last block) =================
    __syncthreads();
    if (tid == 0) {
        const unsigned total = gridDim.x * gridDim.y;
        if (atomicAdd(&g_done, 1u) == total - 1u) {
            g_done = 0;
            g_flag = 0;                 // visible at kernel completion
            __threadfence();
        }
    }
}

// =================== generic fallback (3-kernel, any K/H) ====================
__global__ void __launch_bounds__(CHSZ, 4)
rank_local_kernel(const int* __restrict__ ids, int n) {
    __shared__ int cnt[8 * NBINS];
    const unsigned FULL = 0xffffffffu;
    const int blk = blockIdx.x, tid = threadIdx.x;
    const int w = tid >> 5, lane = tid & 31;
    const int i = blk * CHSZ + tid;
    for (int j = tid; j < 8 * NBINS; j += CHSZ) cnt[j] = 0;
    __syncthreads();
    const bool valid = (i < n);
    const int key = valid ? ids[i] : (NBINS + lane);
    const unsigned mask = __match_any_sync(FULL, key);
    const int lower = __popc(mask & ((1u << lane) - 1u));
    const int leader = __ffs(mask) - 1;
    if (valid && lane == leader) cnt[w * NBINS + key] = __popc(mask);
    __syncthreads();
    if (tid < NBINS) {
        int run = 0;
        #pragma unroll
        for (int ww = 0; ww < 8; ww++) {
            const int h = cnt[ww * NBINS + tid];
            cnt[ww * NBINS + tid] = run;
            run += h;
        }
        g_hist[tid * NCHUNK + blk] = run;
    }
    __syncthreads();
    if (valid) g_inv[i] = lower + cnt[w * NBINS + key];
}

__global__ void __launch_bounds__(NBINS, 1)
scan_kernel(int nchunk) {
    __shared__ int totals[NBINS];
    const int e = threadIdx.x;
    int run = 0;
    #pragma unroll 8
    for (int c = 0; c < nchunk; c++) {
        const int h = g_hist[e * NCHUNK + c];
        g_base[e * NCHUNK + c] = run;
        run += h;
    }
    totals[e] = run;
    __syncthreads();
    #pragma unroll
    for (int d = 1; d < NBINS; d <<= 1) {
        const int v = (e >= d) ? totals[e - d] : 0;
        __syncthreads();
        totals[e] += v;
        __syncthreads();
    }
    g_ebase[e] = (e == 0) ? 0 : totals[e - 1];
}

__global__ void __launch_bounds__(CHSZ, 4)
add_base_kernel(const int* __restrict__ ids, int n) {
    const int i = blockIdx.x * CHSZ + threadIdx.x;
    if (i < n) {
        const int e = ids[i];
        g_inv[i] += g_base[e * NCHUNK + blockIdx.x] + g_ebase[e];
    }
}

__global__ void __launch_bounds__(256, 4)
combine_kernel_gen(const float* __restrict__ G,
                   const float* __restrict__ scales,
                   float* __restrict__ out,
                   int B, int K, int H4, int dup) {
    const int b = blockIdx.y;
    const int h = blockIdx.x * 256 + threadIdx.x;
    __shared__ int   rows[32];
    __shared__ float sc[32];
    if (threadIdx.x < (unsigned)K) {
        rows[threadIdx.x] = g_inv[b * K + threadIdx.x];
        sc[threadIdx.x]   = scales[b * K + threadIdx.x];
    }
    __syncthreads();
    if (h >= H4) return;
    const float4* __restrict__ Gv = reinterpret_cast<const float4*>(G);
    float4* __restrict__ ov = reinterpret_cast<float4*>(out);
    float4 acc = make_float4(0.f, 0.f, 0.f, 0.f);
    for (int k = 0; k < K; k++) {
        const float  s = sc[k];
        const float4 v = __ldg(&Gv[(size_t)rows[k] * H4 + h]);
        acc.x = fmaf(s, v.x, acc.x);
        acc.y = fmaf(s, v.y, acc.y);
        acc.z = fmaf(s, v.z, acc.z);
        acc.w = fmaf(s, v.w, acc.w);
    }
    const size_t o = (size_t)b * H4 + h;
    ov[o] = acc;
    if (dup) ov[(size_t)B * H4 + o] = acc;
}

// ---------------------------------------------------------------------------
extern "C" void kernel_launch(void* const* d_in, const int* in_sizes, int n_in,
                              void* d_out, int out_size) {
    // metadata order: x[B,H] f32, expert_ids[B,K] i32, expert_scales[B,K] f32,
    //                 golden_expand_x[B*K,H] f32, moe_expert_num i32
    const int*   ids    = (const int*)  d_in[1];
    const float* scales = (const float*)d_in[2];
    const float* G      = (const float*)d_in[3];
    float*       out    = (float*)d_out;

    const int N  = in_sizes[1];                     // B*K = 32768
    const long long GH = (long long)in_sizes[3];    // N*H
    const int H  = (int)(GH / N);                   // 4096
    const int B  = in_sizes[0] / H;                 // 4096
    const int K  = N / B;                           // 8
    const int H4 = H >> 2;
    const int dup = (out_size >= 2 * B * H) ? 1 : 0;

    if (K == 8 && N <= MAXN) {
        const int cpb = (H4 + 511) / 512;           // 512 float4 cols / block
        dim3 grid(cpb, B);
        if ((H4 & 511) == 0)
            fused_kernel<8, false><<<grid, 256>>>(ids, scales, G, out,
                                                  B, H4, dup, N);
        else
            fused_kernel<8, true><<<grid, 256>>>(ids, scales, G, out,
                                                 B, H4, dup, N);
    } else {
        const int nchunk = (N + CHSZ - 1) / CHSZ;
        rank_local_kernel<<<nchunk, CHSZ>>>(ids, N);
        scan_kernel<<<1, NBINS>>>(nchunk);
        add_base_kernel<<<nchunk, CHSZ>>>(ids, N);
        const int cpb = (H4 + 255) / 256;
        dim3 grid(cpb, B);
        combine_kernel_gen<<<grid, 256>>>(G, scales, out, B, K, H4, dup);
    }
}

// round 9
// speedup vs baseline: 1.2641x; 1.2641x over previous
#include <cuda_runtime.h>

// ---------------------------------------------------------------------------
// MOE_DISTRIBUTE_CASCADE_GRAPH — two kernels chained by Programmatic
// Dependent Launch (PDL). Measured facts driving this design:
//   * combine is pinned at ~94.4us / 87% DRAM (streaming roofline for 640MB)
//   * single-node replay overhead is ~2.5us (R8), so the ~37us two-node gap
//     is inter-node serialization + rank latency -> hide it with PDL
//   * a single-address reset atomic counter (R8) serializes at ~27cyc/op and
//     throttled the whole chip -> no device flags, no resets, PDL only.
// ---------------------------------------------------------------------------

#define NBINS   256        // max experts supported (dataset uses 64)
#define RWARPS  32         // warps in the rank block
#define RTHREADS (RWARPS * 32)
#define MAXN    65536      // max B*K supported (dataset uses 32768)

__device__ int g_inv[MAXN];

// fallback scratch (generic path)
#define NCHUNK  256
#define CHSZ    256
__device__ int g_hist[NBINS * NCHUNK];
__device__ int g_base[NBINS * NCHUNK];
__device__ int g_ebase[NBINS];

// --- one match-based stable-rank step (warp-converged, FULL mask) ----------
__device__ __forceinline__ void rank_step(int id, int idx, int lane,
                                          int* mycnt) {
    const unsigned FULL = 0xffffffffu;
    const bool valid = (id >= 0);
    const int  key   = valid ? id : (NBINS + lane);     // singleton if invalid
    const unsigned mask = __match_any_sync(FULL, key);
    const int lower  = __popc(mask & ((1u << lane) - 1u));
    const int leader = __ffs(mask) - 1;
    int c0 = 0;
    if (valid && lane == leader) {
        c0 = mycnt[key];
        mycnt[key] = c0 + __popc(mask);
    }
    c0 = __shfl_sync(FULL, c0, leader);
    if (valid) g_inv[idx] = c0 + lower;                 // warp-local rank
    __syncwarp();
}

// --- Kernel 1: fused stable counting-sort rank (single block, R6 body) ------
// Ends with a PDL trigger so the combine grid can launch/ramp concurrently.
__global__ void __launch_bounds__(RTHREADS, 1)
rank_fused_kernel(const int* __restrict__ ids, int n) {
    __shared__ int cnt[RWARPS * NBINS];   // running counters -> bases
    __shared__ int totals[NBINS];

    const int tid  = threadIdx.x;
    const int w    = tid >> 5;
    const int lane = tid & 31;
    const int cpw  = (n + RWARPS - 1) / RWARPS;
    const int beg  = w * cpw;
    const int end  = min(beg + cpw, n);

    for (int i = tid; i < RWARPS * NBINS; i += RTHREADS) cnt[i] = 0;
    __syncthreads();

    int* mycnt = &cnt[w * NBINS];

    // ---- Pass 1: warp-local stable ranks, depth-4 software pipeline --------
    {
        int i = beg + lane;
        int a0 = (i       < end) ? __ldg(&ids[i])       : -1;
        int a1 = (i + 32  < end) ? __ldg(&ids[i + 32])  : -1;
        int a2 = (i + 64  < end) ? __ldg(&ids[i + 64])  : -1;
        int a3 = (i + 96  < end) ? __ldg(&ids[i + 96])  : -1;
        for (int base = beg; base < end; base += 128) {
            const int j = i + 128;
            const int b0 = (j       < end) ? __ldg(&ids[j])       : -1;
            const int b1 = (j + 32  < end) ? __ldg(&ids[j + 32])  : -1;
            const int b2 = (j + 64  < end) ? __ldg(&ids[j + 64])  : -1;
            const int b3 = (j + 96  < end) ? __ldg(&ids[j + 96])  : -1;
            rank_step(a0, i,      lane, mycnt);
            rank_step(a1, i + 32, lane, mycnt);
            rank_step(a2, i + 64, lane, mycnt);
            rank_step(a3, i + 96, lane, mycnt);
            a0 = b0; a1 = b1; a2 = b2; a3 = b3;
            i = j;
        }
    }
    __syncthreads();

    // ---- Scan 1: per-expert exclusive scan over the 32 warp rows -----------
    if (tid < NBINS) {
        int run = 0;
        #pragma unroll
        for (int ww = 0; ww < RWARPS; ww++) {
            const int h = cnt[ww * NBINS + tid];
            cnt[ww * NBINS + tid] = run;
            run += h;
        }
        totals[tid] = run;
    }
    __syncthreads();

    // ---- Scan 2: in-place inclusive Hillis-Steele over expert totals -------
    #pragma unroll
    for (int d = 1; d < NBINS; d <<= 1) {
        const int v = (tid < NBINS && tid >= d) ? totals[tid - d] : 0;
        __syncthreads();
        if (tid < NBINS) totals[tid] += v;
        __syncthreads();
    }
    if (tid < NBINS) {
        const int base = (tid == 0) ? 0 : totals[tid - 1];
        #pragma unroll
        for (int ww = 0; ww < RWARPS; ww++)
            cnt[ww * NBINS + tid] += base;
    }
    __syncthreads();

    // ---- Pass 2: add global bases (independent iterations, ids L1-warm) ----
    #pragma unroll 8
    for (int i = beg + lane; i < end; i += 32)
        g_inv[i] += mycnt[__ldg(&ids[i])];

    // ---- publish + PDL trigger (single block: all writes are done here) ----
    __threadfence();
    __syncthreads();
    cudaTriggerProgrammaticLaunchCompletion();
}

// --- Kernel 2: gather-reduce combine (R6-measured best body + PDL gate) -----
template <int K, bool GUARD>
__global__ void __launch_bounds__(256, 4)
combine_kernel(const float* __restrict__ G,
               const float* __restrict__ scales,
               float* __restrict__ out,
               int B, int H4, int dup) {
    const int b  = blockIdx.y;
    const int h0 = blockIdx.x * 512 + threadIdx.x;
    const int h1 = h0 + 256;
    __shared__ int   rows[K];
    __shared__ float sc[K];

    // rank-independent prefetch overlaps with the rank kernel (PDL)
    if (threadIdx.x < K) sc[threadIdx.x] = scales[b * K + threadIdx.x];

    // wait until rank_fused_kernel's g_inv writes are visible
    cudaGridDependencySynchronize();

    if (threadIdx.x < K) rows[threadIdx.x] = g_inv[b * K + threadIdx.x];
    __syncthreads();

    const float4* __restrict__ Gv = reinterpret_cast<const float4*>(G);
    float4* __restrict__ ov = reinterpret_cast<float4*>(out);

    const bool v0 = GUARD ? (h0 < H4) : true;
    const bool v1 = GUARD ? (h1 < H4) : true;
    float4 acc0 = make_float4(0.f, 0.f, 0.f, 0.f);
    float4 acc1 = make_float4(0.f, 0.f, 0.f, 0.f);
    #pragma unroll
    for (int k = 0; k < K; k++) {
        const float  s  = sc[k];
        const size_t rb = (size_t)rows[k] * H4;
        if (v0) {
            const float4 a = __ldg(&Gv[rb + h0]);
            acc0.x = fmaf(s, a.x, acc0.x);
            acc0.y = fmaf(s, a.y, acc0.y);
            acc0.z = fmaf(s, a.z, acc0.z);
            acc0.w = fmaf(s, a.w, acc0.w);
        }
        if (v1) {
            const float4 c = __ldg(&Gv[rb + h1]);
            acc1.x = fmaf(s, c.x, acc1.x);
            acc1.y = fmaf(s, c.y, acc1.y);
            acc1.z = fmaf(s, c.z, acc1.z);
            acc1.w = fmaf(s, c.w, acc1.w);
        }
    }
    const size_t ob = (size_t)b * H4;
    if (v0) ov[ob + h0] = acc0;
    if (v1) ov[ob + h1] = acc1;
    if (dup) {
        const size_t od = (size_t)B * H4 + ob;
        if (v0) ov[od + h0] = acc0;
        if (v1) ov[od + h1] = acc1;
    }
}

// =================== generic fallback (3-kernel, any K/H) ====================
__global__ void __launch_bounds__(CHSZ, 4)
rank_local_kernel(const int* __restrict__ ids, int n) {
    __shared__ int cnt[8 * NBINS];
    const unsigned FULL = 0xffffffffu;
    const int blk = blockIdx.x, tid = threadIdx.x;
    const int w = tid >> 5, lane = tid & 31;
    const int i = blk * CHSZ + tid;
    for (int j = tid; j < 8 * NBINS; j += CHSZ) cnt[j] = 0;
    __syncthreads();
    const bool valid = (i < n);
    const int key = valid ? ids[i] : (NBINS + lane);
    const unsigned mask = __match_any_sync(FULL, key);
    const int lower = __popc(mask & ((1u << lane) - 1u));
    const int leader = __ffs(mask) - 1;
    if (valid && lane == leader) cnt[w * NBINS + key] = __popc(mask);
    __syncthreads();
    if (tid < NBINS) {
        int run = 0;
        #pragma unroll
        for (int ww = 0; ww < 8; ww++) {
            const int h = cnt[ww * NBINS + tid];
            cnt[ww * NBINS + tid] = run;
            run += h;
        }
        g_hist[tid * NCHUNK + blk] = run;
    }
    __syncthreads();
    if (valid) g_inv[i] = lower + cnt[w * NBINS + key];
}

__global__ void __launch_bounds__(NBINS, 1)
scan_kernel(int nchunk) {
    __shared__ int totals[NBINS];
    const int e = threadIdx.x;
    int run = 0;
    #pragma unroll 8
    for (int c = 0; c < nchunk; c++) {
        const int h = g_hist[e * NCHUNK + c];
        g_base[e * NCHUNK + c] = run;
        run += h;
    }
    totals[e] = run;
    __syncthreads();
    #pragma unroll
    for (int d = 1; d < NBINS; d <<= 1) {
        const int v = (e >= d) ? totals[e - d] : 0;
        __syncthreads();
        totals[e] += v;
        __syncthreads();
    }
    g_ebase[e] = (e == 0) ? 0 : totals[e - 1];
}

__global__ void __launch_bounds__(CHSZ, 4)
add_base_kernel(const int* __restrict__ ids, int n) {
    const int i = blockIdx.x * CHSZ + threadIdx.x;
    if (i < n) {
        const int e = ids[i];
        g_inv[i] += g_base[e * NCHUNK + blockIdx.x] + g_ebase[e];
    }
}

__global__ void __launch_bounds__(256, 4)
combine_kernel_gen(const float* __restrict__ G,
                   const float* __restrict__ scales,
                   float* __restrict__ out,
                   int B, int K, int H4, int dup) {
    const int b = blockIdx.y;
    const int h = blockIdx.x * 256 + threadIdx.x;
    __shared__ int   rows[32];
    __shared__ float sc[32];
    if (threadIdx.x < (unsigned)K) {
        rows[threadIdx.x] = g_inv[b * K + threadIdx.x];
        sc[threadIdx.x]   = scales[b * K + threadIdx.x];
    }
    __syncthreads();
    if (h >= H4) return;
    const float4* __restrict__ Gv = reinterpret_cast<const float4*>(G);
    float4* __restrict__ ov = reinterpret_cast<float4*>(out);
    float4 acc = make_float4(0.f, 0.f, 0.f, 0.f);
    for (int k = 0; k < K; k++) {
        const float  s = sc[k];
        const float4 v = __ldg(&Gv[(size_t)rows[k] * H4 + h]);
        acc.x = fmaf(s, v.x, acc.x);
        acc.y = fmaf(s, v.y, acc.y);
        acc.z = fmaf(s, v.z, acc.z);
        acc.w = fmaf(s, v.w, acc.w);
    }
    const size_t o = (size_t)b * H4 + h;
    ov[o] = acc;
    if (dup) ov[(size_t)B * H4 + o] = acc;
}

// ---------------------------------------------------------------------------
extern "C" void kernel_launch(void* const* d_in, const int* in_sizes, int n_in,
                              void* d_out, int out_size) {
    // metadata order: x[B,H] f32, expert_ids[B,K] i32, expert_scales[B,K] f32,
    //                 golden_expand_x[B*K,H] f32, moe_expert_num i32
    const int*   ids    = (const int*)  d_in[1];
    const float* scales = (const float*)d_in[2];
    const float* G      = (const float*)d_in[3];
    float*       out    = (float*)d_out;

    const int N  = in_sizes[1];                     // B*K = 32768
    const long long GH = (long long)in_sizes[3];    // N*H
    const int H  = (int)(GH / N);                   // 4096
    const int B  = in_sizes[0] / H;                 // 4096
    const int K  = N / B;                           // 8
    const int H4 = H >> 2;
    const int dup = (out_size >= 2 * B * H) ? 1 : 0;

    if (K == 8 && N <= MAXN) {
        rank_fused_kernel<<<1, RTHREADS>>>(ids, N);

        const int cpb = (H4 + 511) / 512;           // 512 float4 cols / block
        dim3 grid(cpb, B);

        cudaLaunchConfig_t cfg = {};
        cfg.gridDim  = grid;
        cfg.blockDim = dim3(256, 1, 1);
        cfg.dynamicSmemBytes = 0;
        cfg.stream = 0;
        cudaLaunchAttribute attrs[1];
        attrs[0].id = cudaLaunchAttributeProgrammaticStreamSerialization;
        attrs[0].val.programmaticStreamSerializationAllowed = 1;
        cfg.attrs = attrs;
        cfg.numAttrs = 1;

        if ((H4 & 511) == 0)
            cudaLaunchKernelEx(&cfg, combine_kernel<8, false>,
                               G, scales, out, B, H4, dup);
        else
            cudaLaunchKernelEx(&cfg, combine_kernel<8, true>,
                               G, scales, out, B, H4, dup);
    } else {
        const int nchunk = (N + CHSZ - 1) / CHSZ;
        rank_local_kernel<<<nchunk, CHSZ>>>(ids, N);
        scan_kernel<<<1, NBINS>>>(nchunk);
        add_base_kernel<<<nchunk, CHSZ>>>(ids, N);
        const int cpb = (H4 + 255) / 256;
        dim3 grid(cpb, B);
        combine_kernel_gen<<<grid, 256>>>(G, scales, out, B, K, H4, dup);
    }
}